// round 3
// baseline (speedup 1.0000x reference)
#include <cuda_runtime.h>
#include <math.h>

#define VOCAB   50257
#define DIM     512
#define MAXDEP  20
#define HALF    10            // depths per warp (2 warps per token)
#define NTOK    8192          // B*S = 8*1024
#define NWARP   (NTOK * 2)    // 2 warps per token
#define NBLOCK  (NWARP / 8)   // 8 warps per 256-thread block -> 2048 blocks

// Scratch (allocation-free per harness rules).
__device__ float        g_partials[NBLOCK];
__device__ unsigned int g_count = 0;   // self-resets each launch -> graph-safe

__global__ void __launch_bounds__(256) hs_fused_kernel(
    const float* __restrict__ hidden,      // [NTOK, DIM]
    const float* __restrict__ node_emb,    // [VOCAB-1, DIM]
    const float* __restrict__ path_signs,  // [VOCAB, MAXDEP]
    const int*   __restrict__ targets,     // [NTOK]
    const int*   __restrict__ path_nodes,  // [VOCAB, MAXDEP]
    const int*   __restrict__ path_lens,   // [VOCAB]
    float*       __restrict__ out)
{
    __shared__ float s_warp[8];

    const int warp = threadIdx.x >> 5;
    const int lane = threadIdx.x & 31;
    const int gw   = blockIdx.x * 8 + warp;
    const int tok  = gw >> 1;              // token index
    const int half = gw & 1;               // which half of the path

    const int t   = targets[tok];
    int       len = path_lens[t];
    if (len < 1) len = 1;

    const int d0 = half * HALF;
    const int nd = min(len, d0 + HALF) - d0;   // #depths this warp handles

    float nll = 0.0f;

    if (nd > 0) {
        // Coalesced preload of this warp's slice of path metadata.
        int   my_node = 0;
        float my_sign = 1.0f;
        if (lane < HALF) {
            my_node = path_nodes[(size_t)t * MAXDEP + d0 + lane];
            my_sign = (path_signs[(size_t)t * MAXDEP + d0 + lane] >= 0.0f)
                          ? 1.0f : -1.0f;
        }

        // Hidden row in registers: 16 floats/lane, coalesced (L1-hot for 2nd warp).
        const float4* h4 = reinterpret_cast<const float4*>(hidden + (size_t)tok * DIM);
        const float4 h0 = h4[lane];
        const float4 h1 = h4[lane + 32];
        const float4 h2 = h4[lane + 64];
        const float4 h3 = h4[lane + 96];

        // Fixed 10-trip fully-unrolled predicated loop: independent gathers batch.
        #pragma unroll
        for (int i = 0; i < HALF; ++i) {
            if (i < nd) {
                const int node = __shfl_sync(0xffffffffu, my_node, i);
                const float4* w4 =
                    reinterpret_cast<const float4*>(node_emb + (size_t)node * DIM);
                const float4 w0 = w4[lane];
                const float4 w1 = w4[lane + 32];
                const float4 w2 = w4[lane + 64];
                const float4 w3 = w4[lane + 96];

                float acc;
                acc = h0.x * w0.x;            acc = fmaf(h0.y, w0.y, acc);
                acc = fmaf(h0.z, w0.z, acc);  acc = fmaf(h0.w, w0.w, acc);
                acc = fmaf(h1.x, w1.x, acc);  acc = fmaf(h1.y, w1.y, acc);
                acc = fmaf(h1.z, w1.z, acc);  acc = fmaf(h1.w, w1.w, acc);
                acc = fmaf(h2.x, w2.x, acc);  acc = fmaf(h2.y, w2.y, acc);
                acc = fmaf(h2.z, w2.z, acc);  acc = fmaf(h2.w, w2.w, acc);
                acc = fmaf(h3.x, w3.x, acc);  acc = fmaf(h3.y, w3.y, acc);
                acc = fmaf(h3.z, w3.z, acc);  acc = fmaf(h3.w, w3.w, acc);

                #pragma unroll
                for (int off = 16; off > 0; off >>= 1)
                    acc += __shfl_xor_sync(0xffffffffu, acc, off);

                const float s = __shfl_sync(0xffffffffu, my_sign, i);
                const float z = s * acc;
                // -log sigmoid(z) = max(-z,0) + log1p(exp(-|z|))   (stable)
                nll += fmaxf(-z, 0.0f) + log1pf(expf(-fabsf(z)));
            }
        }
    }

    if (lane == 0) s_warp[warp] = nll;
    __syncthreads();

    if (threadIdx.x == 0) {
        float bs = 0.0f;
        #pragma unroll
        for (int i = 0; i < 8; ++i) bs += s_warp[i];
        g_partials[blockIdx.x] = bs;
    }
    __threadfence();

    // Last-block-done pattern: one block deterministically reduces all partials.
    __shared__ unsigned int s_last;
    if (threadIdx.x == 0)
        s_last = (atomicAdd(&g_count, 1u) == (unsigned)(gridDim.x - 1));
    __syncthreads();

    if (s_last) {
        float s = 0.0f;
        #pragma unroll
        for (int i = 0; i < NBLOCK / 256; ++i)
            s += g_partials[threadIdx.x + i * 256];

        __shared__ float sm[256];
        sm[threadIdx.x] = s;
        __syncthreads();
        #pragma unroll
        for (int k = 128; k > 0; k >>= 1) {
            if (threadIdx.x < k) sm[threadIdx.x] += sm[threadIdx.x + k];
            __syncthreads();
        }
        if (threadIdx.x == 0) {
            out[0]  = sm[0] * (1.0f / (float)NTOK);
            g_count = 0;   // reset for next launch / graph replay
        }
    }
}

extern "C" void kernel_launch(void* const* d_in, const int* in_sizes, int n_in,
                              void* d_out, int out_size)
{
    const float* hidden     = (const float*)d_in[0];
    const float* node_emb   = (const float*)d_in[1];
    const float* path_signs = (const float*)d_in[2];
    const int*   targets    = (const int*)  d_in[3];
    const int*   path_nodes = (const int*)  d_in[4];
    const int*   path_lens  = (const int*)  d_in[5];
    float*       out        = (float*)d_out;

    hs_fused_kernel<<<NBLOCK, 256>>>(hidden, node_emb, path_signs,
                                     targets, path_nodes, path_lens, out);
}

// round 4
// speedup vs baseline: 1.0402x; 1.0402x over previous
#include <cuda_runtime.h>
#include <math.h>

#define VOCAB   50257
#define DIM     512
#define MAXDEP  20
#define CHUNK   5
#define NTOK    8192          // B*S
#define NBLOCK  (NTOK / 8)    // 8 warps (tokens) per 256-thread block

__device__ float        g_partials[NBLOCK];
__device__ unsigned int g_count = 0;   // self-resets -> graph-replay safe

__global__ void __launch_bounds__(256, 2) hs_fused_kernel(
    const float* __restrict__ hidden,      // [NTOK, DIM]
    const float* __restrict__ node_emb,    // [VOCAB-1, DIM]
    const float* __restrict__ path_signs,  // [VOCAB, MAXDEP]
    const int*   __restrict__ targets,     // [NTOK]
    const int*   __restrict__ path_nodes,  // [VOCAB, MAXDEP]
    const int*   __restrict__ path_lens,   // [VOCAB]
    float*       __restrict__ out)
{
    __shared__ float s_warp[8];

    const int warp = threadIdx.x >> 5;
    const int lane = threadIdx.x & 31;
    const int tok  = blockIdx.x * 8 + warp;

    const int t   = targets[tok];
    int       len = path_lens[t];
    if (len < 1) len = 1;

    // Coalesced preload of path metadata; broadcast via shfl at use sites.
    int   my_node = 0;
    float my_sign = 1.0f;
    if (lane < MAXDEP) {
        my_node = path_nodes[(size_t)t * MAXDEP + lane];
        my_sign = (path_signs[(size_t)t * MAXDEP + lane] >= 0.0f) ? 1.0f : -1.0f;
    }

    // Hidden row: 16 floats/lane in registers.
    const float4* h4 = reinterpret_cast<const float4*>(hidden + (size_t)tok * DIM);
    const float4 h0 = h4[lane];
    const float4 h1 = h4[lane + 32];
    const float4 h2 = h4[lane + 64];
    const float4 h3 = h4[lane + 96];

    float nll = 0.0f;
    const int nchunks = (len + CHUNK - 1) / CHUNK;   // warp-uniform, 1..4

    for (int c = 0; c < nchunks; ++c) {
        const int base = c * CHUNK;

        // ---- Phase 1: issue ALL 20 gather loads of this chunk (branch-free).
        // Out-of-range depths clamp to len-1 -> same row already in flight/L1.
        float4 w[CHUNK][4];
        #pragma unroll
        for (int i = 0; i < CHUNK; ++i) {
            int d  = base + i;
            int dc = (d < len) ? d : (len - 1);
            const int node = __shfl_sync(0xffffffffu, my_node, dc);
            const float4* w4 =
                reinterpret_cast<const float4*>(node_emb + (size_t)node * DIM);
            w[i][0] = w4[lane];
            w[i][1] = w4[lane + 32];
            w[i][2] = w4[lane + 64];
            w[i][3] = w4[lane + 96];
        }

        // ---- Phase 2: per-lane partial dots (no shfl in the load shadow).
        float p[CHUNK];
        #pragma unroll
        for (int i = 0; i < CHUNK; ++i) {
            float a;
            a = h0.x * w[i][0].x;          a = fmaf(h0.y, w[i][0].y, a);
            a = fmaf(h0.z, w[i][0].z, a);  a = fmaf(h0.w, w[i][0].w, a);
            a = fmaf(h1.x, w[i][1].x, a);  a = fmaf(h1.y, w[i][1].y, a);
            a = fmaf(h1.z, w[i][1].z, a);  a = fmaf(h1.w, w[i][1].w, a);
            a = fmaf(h2.x, w[i][2].x, a);  a = fmaf(h2.y, w[i][2].y, a);
            a = fmaf(h2.z, w[i][2].z, a);  a = fmaf(h2.w, w[i][2].w, a);
            a = fmaf(h3.x, w[i][3].x, a);  a = fmaf(h3.y, w[i][3].y, a);
            a = fmaf(h3.z, w[i][3].w * 0.0f + w[i][3].z, a);
            a = fmaf(h3.w, w[i][3].w, a);
            p[i] = a;
        }

        // ---- Phase 3: 5 independent butterfly reductions (interleaved by HW).
        #pragma unroll
        for (int off = 16; off > 0; off >>= 1) {
            #pragma unroll
            for (int i = 0; i < CHUNK; ++i)
                p[i] += __shfl_xor_sync(0xffffffffu, p[i], off);
        }

        // ---- Phase 4: NLL contributions (all lanes redundantly; warp-uniform).
        #pragma unroll
        for (int i = 0; i < CHUNK; ++i) {
            const int d = base + i;
            if (d < len) {
                const float s = __shfl_sync(0xffffffffu, my_sign, d);
                const float z = s * p[i];
                nll += fmaxf(-z, 0.0f) + log1pf(expf(-fabsf(z)));
            }
        }
    }

    if (lane == 0) s_warp[warp] = nll;
    __syncthreads();

    if (threadIdx.x == 0) {
        float bs = 0.0f;
        #pragma unroll
        for (int i = 0; i < 8; ++i) bs += s_warp[i];
        g_partials[blockIdx.x] = bs;
    }
    __threadfence();

    __shared__ unsigned int s_last;
    if (threadIdx.x == 0)
        s_last = (atomicAdd(&g_count, 1u) == (unsigned)(gridDim.x - 1));
    __syncthreads();

    if (s_last) {
        float s = 0.0f;
        #pragma unroll
        for (int i = 0; i < NBLOCK / 256; ++i)
            s += g_partials[threadIdx.x + i * 256];

        __shared__ float sm[256];
        sm[threadIdx.x] = s;
        __syncthreads();
        #pragma unroll
        for (int k = 128; k > 0; k >>= 1) {
            if (threadIdx.x < k) sm[threadIdx.x] += sm[threadIdx.x + k];
            __syncthreads();
        }
        if (threadIdx.x == 0) {
            out[0]  = sm[0] * (1.0f / (float)NTOK);
            g_count = 0;
        }
    }
}

extern "C" void kernel_launch(void* const* d_in, const int* in_sizes, int n_in,
                              void* d_out, int out_size)
{
    const float* hidden     = (const float*)d_in[0];
    const float* node_emb   = (const float*)d_in[1];
    const float* path_signs = (const float*)d_in[2];
    const int*   targets    = (const int*)  d_in[3];
    const int*   path_nodes = (const int*)  d_in[4];
    const int*   path_lens  = (const int*)  d_in[5];
    float*       out        = (float*)d_out;

    hs_fused_kernel<<<NBLOCK, 256>>>(hidden, node_emb, path_signs,
                                     targets, path_nodes, path_lens, out);
}

// round 7
// speedup vs baseline: 1.3481x; 1.2960x over previous
#include <cuda_runtime.h>
#include <math.h>

#define VOCAB   50257
#define DIM     512
#define MAXDEP  20
#define NTOK    8192            // B*S
#define WPB     4               // warps (tokens) per 128-thread block
#define NBLOCK  (NTOK / WPB)    // 2048 blocks

__device__ float        g_partials[NBLOCK];
__device__ unsigned int g_count = 0;   // self-resets -> graph-replay safe

__global__ void __launch_bounds__(128) hs_kernel(
    const float* __restrict__ hidden,      // [NTOK, DIM]
    const float* __restrict__ node_emb,    // [VOCAB-1, DIM]
    const float* __restrict__ path_signs,  // [VOCAB, MAXDEP]
    const int*   __restrict__ targets,     // [NTOK]
    const int*   __restrict__ path_nodes,  // [VOCAB, MAXDEP]
    const int*   __restrict__ path_lens,   // [VOCAB]
    float*       __restrict__ out)
{
    __shared__ float s_warp[WPB];

    const int warp = threadIdx.x >> 5;
    const int lane = threadIdx.x & 31;
    const int tok  = blockIdx.x * WPB + warp;

    const int t   = targets[tok];
    int       len = path_lens[t];
    if (len < 1) len = 1;

    // Coalesced preload of path metadata; broadcast via shfl at use sites.
    int   my_node = 0;
    float my_sign = 1.0f;
    if (lane < MAXDEP) {
        my_node = path_nodes[(size_t)t * MAXDEP + lane];
        my_sign = (path_signs[(size_t)t * MAXDEP + lane] >= 0.0f) ? 1.0f : -1.0f;
    }

    // Hidden row: 16 floats/lane in registers.
    const float4* h4 = reinterpret_cast<const float4*>(hidden + (size_t)tok * DIM);
    const float4 h0 = h4[lane];
    const float4 h1 = h4[lane + 32];
    const float4 h2 = h4[lane + 64];
    const float4 h3 = h4[lane + 96];

    // ---- Prologue: load row 0 into the current buffer.
    float4 c0, c1, c2, c3;
    {
        const int node = __shfl_sync(0xffffffffu, my_node, 0);
        const float4* w4 =
            reinterpret_cast<const float4*>(node_emb + (size_t)node * DIM);
        c0 = w4[lane]; c1 = w4[lane + 32]; c2 = w4[lane + 64]; c3 = w4[lane + 96];
    }

    float nll = 0.0f;

    // ---- 2-deep software pipeline: prefetch row d+1 while computing row d.
    for (int d = 0; d < len; ++d) {
        // Branch-free prefetch: clamp to len-1 (last iter reloads L1-hot row).
        const int dn   = (d + 1 < len) ? (d + 1) : (len - 1);
        const int node = __shfl_sync(0xffffffffu, my_node, dn);
        const float4* w4 =
            reinterpret_cast<const float4*>(node_emb + (size_t)node * DIM);
        const float4 n0 = w4[lane];
        const float4 n1 = w4[lane + 32];
        const float4 n2 = w4[lane + 64];
        const float4 n3 = w4[lane + 96];

        // Compute with current buffer while the 4 prefetch LDG.128 are in flight.
        float a;
        a = h0.x * c0.x;           a = fmaf(h0.y, c0.y, a);
        a = fmaf(h0.z, c0.z, a);   a = fmaf(h0.w, c0.w, a);
        a = fmaf(h1.x, c1.x, a);   a = fmaf(h1.y, c1.y, a);
        a = fmaf(h1.z, c1.z, a);   a = fmaf(h1.w, c1.w, a);
        a = fmaf(h2.x, c2.x, a);   a = fmaf(h2.y, c2.y, a);
        a = fmaf(h2.z, c2.z, a);   a = fmaf(h2.w, c2.w, a);
        a = fmaf(h3.x, c3.x, a);   a = fmaf(h3.y, c3.y, a);
        a = fmaf(h3.z, c3.z, a);   a = fmaf(h3.w, c3.w, a);

        #pragma unroll
        for (int off = 16; off > 0; off >>= 1)
            a += __shfl_xor_sync(0xffffffffu, a, off);

        const float sgn = __shfl_sync(0xffffffffu, my_sign, d);
        const float z   = sgn * a;
        // -log sigmoid(z) = max(-z,0) + log1p(exp(-|z|))   (stable)
        nll += fmaxf(-z, 0.0f) + log1pf(expf(-fabsf(z)));

        // Rotate buffers (register moves; cheap vs. the saved latency).
        c0 = n0; c1 = n1; c2 = n2; c3 = n3;
    }

    if (lane == 0) s_warp[warp] = nll;
    __syncthreads();

    if (threadIdx.x == 0) {
        float bs = 0.0f;
        #pragma unroll
        for (int i = 0; i < WPB; ++i) bs += s_warp[i];
        g_partials[blockIdx.x] = bs;
    }
    __threadfence();

    // Last-block-done: one block deterministically reduces all partials.
    __shared__ unsigned int s_last;
    if (threadIdx.x == 0)
        s_last = (atomicAdd(&g_count, 1u) == (unsigned)(gridDim.x - 1));
    __syncthreads();

    if (s_last) {
        float s = 0.0f;
        #pragma unroll
        for (int i = 0; i < NBLOCK / 128; ++i)
            s += g_partials[threadIdx.x + i * 128];

        __shared__ float sm[128];
        sm[threadIdx.x] = s;
        __syncthreads();
        #pragma unroll
        for (int k = 64; k > 0; k >>= 1) {
            if (threadIdx.x < k) sm[threadIdx.x] += sm[threadIdx.x + k];
            __syncthreads();
        }
        if (threadIdx.x == 0) {
            out[0]  = sm[0] * (1.0f / (float)NTOK);
            g_count = 0;   // reset for next launch / graph replay
        }
    }
}

extern "C" void kernel_launch(void* const* d_in, const int* in_sizes, int n_in,
                              void* d_out, int out_size)
{
    const float* hidden     = (const float*)d_in[0];
    const float* node_emb   = (const float*)d_in[1];
    const float* path_signs = (const float*)d_in[2];
    const int*   targets    = (const int*)  d_in[3];
    const int*   path_nodes = (const int*)  d_in[4];
    const int*   path_lens  = (const int*)  d_in[5];
    float*       out        = (float*)d_out;

    hs_kernel<<<NBLOCK, 128>>>(hidden, node_emb, path_signs,
                               targets, path_nodes, path_lens, out);
}